// round 1
// baseline (speedup 1.0000x reference)
#include <cuda_runtime.h>
#include <cstdint>

// Problem constants (fixed by setup_inputs)
#define BB 8
#define NN 8192
#define NPOINT 1024
#define NSAMPLE 32
#define DD 64
#define R2 0.0625f
#define OUTCH 67  // 3 + 64

__device__ __forceinline__ float fmul(float a, float b) { return __fmul_rn(a, b); }
__device__ __forceinline__ float fadd(float a, float b) { return __fadd_rn(a, b); }
__device__ __forceinline__ float fsub(float a, float b) { return __fsub_rn(a, b); }

// ---------------------------------------------------------------------------
// Kernel 1: farthest point sampling. One CTA (1024 threads) per batch.
// Each thread owns 8 points in registers (coords + running min-dist).
// Per step: broadcast centroid via L1 (same-address LDG), update dists,
// block argmax with first-index tie-break (matches jnp.argmax), emit new_xyz.
// Collected index at step t is the "farthest" BEFORE the update (scan semantics:
// first collected index is 0).
// ---------------------------------------------------------------------------
__global__ void __launch_bounds__(1024, 1)
fps_kernel(const float* __restrict__ xyz, float* __restrict__ new_xyz) {
    const int b   = blockIdx.x;
    const int tid = threadIdx.x;
    const float* xb = xyz + (size_t)b * NN * 3;

    float px[8], py[8], pz[8], dist[8];
#pragma unroll
    for (int k = 0; k < 8; k++) {
        int j = tid + k * 1024;
        px[k]   = __ldg(xb + j * 3 + 0);
        py[k]   = __ldg(xb + j * 3 + 1);
        pz[k]   = __ldg(xb + j * 3 + 2);
        dist[k] = 1e10f;  // 10000000000.0 rounds to 1e10f in fp32
    }

    __shared__ unsigned long long warp_key[32];
    __shared__ int sh_f;

    int f = 0;
    float* ob = new_xyz + (size_t)b * NPOINT * 3;

    for (int it = 0; it < NPOINT; it++) {
        // centroid = xyz[f] ; broadcast load (all threads same address -> L1 bcast)
        float cx = __ldg(xb + f * 3 + 0);
        float cy = __ldg(xb + f * 3 + 1);
        float cz = __ldg(xb + f * 3 + 2);
        if (tid == 0) {  // collected idx at this step is f (pre-update)
            ob[it * 3 + 0] = cx;
            ob[it * 3 + 1] = cy;
            ob[it * 3 + 2] = cz;
        }

        float bv = -1.0f;
        int   bi = 0;
#pragma unroll
        for (int k = 0; k < 8; k++) {
            // exact arithmetic order of jnp: sum((xyz - c)**2) = ((dx*dx + dy*dy) + dz*dz)
            float dx = fsub(px[k], cx);
            float dy = fsub(py[k], cy);
            float dz = fsub(pz[k], cz);
            float d  = fadd(fadd(fmul(dx, dx), fmul(dy, dy)), fmul(dz, dz));
            float nd = fminf(dist[k], d);
            dist[k]  = nd;
            // strict '>' keeps smallest index within the thread (k ascending)
            if (nd > bv) { bv = nd; bi = tid + k * 1024; }
        }

        // Pack: high 32 = float bits of value (nonneg -> monotonic),
        // low 32 = (N-1 - idx) so max key picks smallest index on value ties.
        unsigned long long key =
            ((unsigned long long)__float_as_uint(bv) << 32) |
            (unsigned)(NN - 1 - bi);
#pragma unroll
        for (int o = 16; o > 0; o >>= 1) {
            unsigned long long other = __shfl_xor_sync(0xffffffffu, key, o);
            if (other > key) key = other;
        }
        if ((tid & 31) == 0) warp_key[tid >> 5] = key;
        __syncthreads();
        if (tid < 32) {
            key = warp_key[tid];
#pragma unroll
            for (int o = 16; o > 0; o >>= 1) {
                unsigned long long other = __shfl_xor_sync(0xffffffffu, key, o);
                if (other > key) key = other;
            }
            if (tid == 0) sh_f = NN - 1 - (int)(unsigned)(key & 0xffffffffu);
        }
        __syncthreads();
        f = sh_f;
    }
}

// ---------------------------------------------------------------------------
// Kernel 2: ball query + gather + concat. One warp per centroid (8192 warps).
// Scans points in index order, collects the first 32 with d <= r^2 via ballot
// ordered-append (exactly sort(where(...))[ :32 ] semantics), pads with the
// first index, then gathers xyz (centered) and the 64 feature channels.
// Distance uses the reference's EXPANDED formula with einsum summation order.
// ---------------------------------------------------------------------------
__global__ void __launch_bounds__(256)
ball_kernel(const float* __restrict__ xyz, const float* __restrict__ points,
            const float* __restrict__ new_xyz, float* __restrict__ new_points) {
    const int w    = threadIdx.x >> 5;
    const int lane = threadIdx.x & 31;
    const int gw   = blockIdx.x * 8 + w;    // global warp id = centroid id
    const int b    = gw >> 10;              // / NPOINT
    const int m    = gw & (NPOINT - 1);

    const float* xb = xyz + (size_t)b * NN * 3;
    const float* c  = new_xyz + ((size_t)b * NPOINT + m) * 3;
    const float sx = c[0], sy = c[1], sz = c[2];
    const float sn = fadd(fadd(fmul(sx, sx), fmul(sy, sy)), fmul(sz, sz));

    __shared__ int sel[8][NSAMPLE];

    int cnt = 0;
    for (int base = 0; base < NN; base += 32) {
        int j = base + lane;
        float x = __ldg(xb + j * 3 + 0);
        float y = __ldg(xb + j * 3 + 1);
        float z = __ldg(xb + j * 3 + 2);
        // sqr = (-2*dot + |src|^2) + |dst|^2, dot = ((sx*x + sy*y) + sz*z)
        float dot = fadd(fadd(fmul(sx, x), fmul(sy, y)), fmul(sz, z));
        float dn  = fadd(fadd(fmul(x, x), fmul(y, y)), fmul(z, z));
        float t   = fadd(fadd(fmul(-2.0f, dot), sn), dn);
        bool  q   = (t <= R2);
        unsigned mask = __ballot_sync(0xffffffffu, q);
        if (q) {
            int p = cnt + __popc(mask & ((1u << lane) - 1u));
            if (p < NSAMPLE) sel[w][p] = j;
        }
        cnt += __popc(mask);
        if (cnt >= NSAMPLE) break;   // uniform across warp
    }
    __syncwarp();

    // pad with first index (at least one point always qualifies: the centroid)
    int cfull = cnt < NSAMPLE ? cnt : NSAMPLE;
    int first = sel[w][0];
    __syncwarp();
    if (lane >= cfull) sel[w][lane] = first;
    __syncwarp();

    const int idx = sel[w][lane];

    float gx = fsub(__ldg(xb + idx * 3 + 0), sx);
    float gy = fsub(__ldg(xb + idx * 3 + 1), sy);
    float gz = fsub(__ldg(xb + idx * 3 + 2), sz);

    float* op = new_points + (((size_t)(b * NPOINT + m)) * NSAMPLE + lane) * OUTCH;
    op[0] = gx; op[1] = gy; op[2] = gz;

    const float4* pp =
        reinterpret_cast<const float4*>(points + ((size_t)b * NN + idx) * DD);
#pragma unroll
    for (int i = 0; i < 16; i++) {
        float4 v = __ldg(pp + i);
        op[3 + 4 * i + 0] = v.x;
        op[3 + 4 * i + 1] = v.y;
        op[3 + 4 * i + 2] = v.z;
        op[3 + 4 * i + 3] = v.w;
    }
}

// ---------------------------------------------------------------------------
extern "C" void kernel_launch(void* const* d_in, const int* in_sizes, int n_in,
                              void* d_out, int out_size) {
    const float* xyz    = (const float*)d_in[0];
    const float* points = (const float*)d_in[1];
    // d_in[2..4] = npoint / radius / nsample scalars; fixed by problem, hardcoded.

    float* new_xyz    = (float*)d_out;
    float* new_points = (float*)d_out + (size_t)BB * NPOINT * 3;

    fps_kernel<<<BB, 1024>>>(xyz, new_xyz);
    ball_kernel<<<(BB * NPOINT) / 8, 256>>>(xyz, points, new_xyz, new_points);
}

// round 2
// speedup vs baseline: 1.3810x; 1.3810x over previous
#include <cuda_runtime.h>
#include <cstdint>

// Problem constants (fixed by setup_inputs)
#define BB 8
#define NN 8192
#define NPOINT 1024
#define NSAMPLE 32
#define DD 64
#define R2 0.0625f
#define OUTCH 67  // 3 + 64

using u64 = unsigned long long;

// ---- packed f32x2 helpers (per-lane IEEE RN, bit-identical to scalar __f*_rn)
__device__ __forceinline__ u64 pk2(float lo, float hi) {
    u64 r; asm("mov.b64 %0, {%1,%2};" : "=l"(r) : "f"(lo), "f"(hi)); return r;
}
__device__ __forceinline__ void up2(u64 v, float& lo, float& hi) {
    asm("mov.b64 {%0,%1}, %2;" : "=f"(lo), "=f"(hi) : "l"(v));
}
__device__ __forceinline__ u64 add2(u64 a, u64 b) {
    u64 r; asm("add.rn.f32x2 %0, %1, %2;" : "=l"(r) : "l"(a), "l"(b)); return r;
}
__device__ __forceinline__ u64 mul2(u64 a, u64 b) {
    u64 r; asm("mul.rn.f32x2 %0, %1, %2;" : "=l"(r) : "l"(a), "l"(b)); return r;
}

// ---------------------------------------------------------------------------
// Kernel 1: farthest point sampling. One CTA (1024 threads) per batch.
// 8 points/thread in registers, packed as f32x2 pairs. Per step:
//   - packed distance update:  d = ((dx*dx + dy*dy) + dz*dz), exact jnp order
//     (subtraction realized as add of exact negation: bit-identical)
//   - value-only max via fmax + __reduce_max_sync on float bits (nonneg ->
//     u32-monotonic), block reduce through smem
//   - index recovery: threads holding dist bits == max do atomicMin(index)
//     (= jnp.argmax first-occurrence tie-break)
// ---------------------------------------------------------------------------
__global__ void __launch_bounds__(1024, 1)
fps_kernel(const float* __restrict__ xyz, float* __restrict__ new_xyz) {
    const int b   = blockIdx.x;
    const int tid = threadIdx.x;
    const float* xb = xyz + (size_t)b * NN * 3;

    u64 px2[4], py2[4], pz2[4];
    float dist[8];
#pragma unroll
    for (int p = 0; p < 4; p++) {
        int j0 = tid + (2 * p) * 1024;
        int j1 = tid + (2 * p + 1) * 1024;
        px2[p] = pk2(__ldg(xb + j0 * 3 + 0), __ldg(xb + j1 * 3 + 0));
        py2[p] = pk2(__ldg(xb + j0 * 3 + 1), __ldg(xb + j1 * 3 + 1));
        pz2[p] = pk2(__ldg(xb + j0 * 3 + 2), __ldg(xb + j1 * 3 + 2));
    }
#pragma unroll
    for (int k = 0; k < 8; k++) dist[k] = 1e10f;  // 1e10 rounds to 1e10f

    __shared__ unsigned warp_max[32];
    __shared__ unsigned sh_mv;
    __shared__ int sh_best;

    int f = 0;
    float* ob = new_xyz + (size_t)b * NPOINT * 3;

    for (int it = 0; it < NPOINT; it++) {
        float cx = __ldg(xb + f * 3 + 0);
        float cy = __ldg(xb + f * 3 + 1);
        float cz = __ldg(xb + f * 3 + 2);
        if (tid == 0) {  // collected index at step t is f (pre-update)
            ob[it * 3 + 0] = cx;
            ob[it * 3 + 1] = cy;
            ob[it * 3 + 2] = cz;
        }
        u64 ncx = pk2(-cx, -cx), ncy = pk2(-cy, -cy), ncz = pk2(-cz, -cz);

        float vmax = -1.0f;
#pragma unroll
        for (int p = 0; p < 4; p++) {
            u64 dx = add2(px2[p], ncx);           // px - cx, exact
            u64 dy = add2(py2[p], ncy);
            u64 dz = add2(pz2[p], ncz);
            u64 d2 = add2(add2(mul2(dx, dx), mul2(dy, dy)), mul2(dz, dz));
            float d0, d1; up2(d2, d0, d1);
            float n0 = fminf(dist[2 * p], d0);
            float n1 = fminf(dist[2 * p + 1], d1);
            dist[2 * p] = n0; dist[2 * p + 1] = n1;
            vmax = fmaxf(vmax, fmaxf(n0, n1));
        }

        unsigned uv = __reduce_max_sync(0xffffffffu, __float_as_uint(vmax));
        if ((tid & 31) == 0) warp_max[tid >> 5] = uv;
        __syncthreads();
        if (tid < 32) {
            unsigned v = warp_max[tid];
            unsigned r = __reduce_max_sync(0xffffffffu, v);
            if (tid == 0) { sh_mv = r; sh_best = 0x7fffffff; }
        }
        __syncthreads();
        const unsigned mv = sh_mv;
        int cand = 0x7fffffff;
#pragma unroll
        for (int k = 0; k < 8; k++)
            if (cand == 0x7fffffff && __float_as_uint(dist[k]) == mv)
                cand = tid + k * 1024;   // k ascending -> smallest idx in thread
        if (cand != 0x7fffffff) atomicMin(&sh_best, cand);
        __syncthreads();
        f = sh_best;
    }
}

// ---------------------------------------------------------------------------
// Kernel 2: ball query + gather + concat. One warp per centroid, 8 warps/CTA,
// all 8 warps of a CTA share the same batch. xyz is staged through smem tiles
// (12 KB, AoS; stride-3 LDS is bank-conflict-free since gcd(3,32)=1).
// Selection = first 32 indices with d<=r^2 in index order (ballot append),
// pad with first. Gather is channel-major: per sample the warp reads one
// contiguous 256B feature row and stores 67 floats near-coalesced.
// ---------------------------------------------------------------------------
#define TILE 1024
__global__ void __launch_bounds__(256)
ball_kernel(const float* __restrict__ xyz, const float* __restrict__ points,
            const float* __restrict__ new_xyz, float* __restrict__ new_points) {
    __shared__ float sxyz[TILE * 3];
    __shared__ int sel[8][NSAMPLE];

    const int tid  = threadIdx.x;
    const int w    = tid >> 5;
    const int lane = tid & 31;
    const int gw   = blockIdx.x * 8 + w;    // centroid id
    const int b    = gw >> 10;
    const int m    = gw & (NPOINT - 1);

    const float* xb = xyz + (size_t)b * NN * 3;
    const float* c  = new_xyz + ((size_t)b * NPOINT + m) * 3;
    const float sx = c[0], sy = c[1], sz = c[2];
    const float sn = __fadd_rn(__fadd_rn(__fmul_rn(sx, sx), __fmul_rn(sy, sy)),
                               __fmul_rn(sz, sz));

    int cnt = 0;
    bool done = false;
    for (int t = 0; t < NN / TILE; t++) {
        if (__syncthreads_and(done ? 1 : 0)) break;  // uniform early-out + barrier
        {   // cooperative tile load: 3072 floats = 768 float4, 3 per thread
            const float4* src = (const float4*)(xb + (size_t)t * TILE * 3);
            float4* dst = (float4*)sxyz;
            dst[tid]       = __ldg(src + tid);
            dst[tid + 256] = __ldg(src + tid + 256);
            dst[tid + 512] = __ldg(src + tid + 512);
        }
        __syncthreads();
        if (!done) {
            for (int base = 0; base < TILE; base += 32) {
                int j = base + lane;
                float x = sxyz[j * 3 + 0];
                float y = sxyz[j * 3 + 1];
                float z = sxyz[j * 3 + 2];
                // sqr = (-2*dot + |src|^2) + |dst|^2, dot = ((sx*x+sy*y)+sz*z)
                float dot = __fadd_rn(__fadd_rn(__fmul_rn(sx, x), __fmul_rn(sy, y)),
                                      __fmul_rn(sz, z));
                float dn  = __fadd_rn(__fadd_rn(__fmul_rn(x, x), __fmul_rn(y, y)),
                                      __fmul_rn(z, z));
                float q   = __fadd_rn(__fadd_rn(__fmul_rn(-2.0f, dot), sn), dn);
                bool ok = (q <= R2);
                unsigned msk = __ballot_sync(0xffffffffu, ok);
                if (ok) {
                    int p = cnt + __popc(msk & ((1u << lane) - 1u));
                    if (p < NSAMPLE) sel[w][p] = t * TILE + j;
                }
                cnt += __popc(msk);
                if (cnt >= NSAMPLE) { done = true; break; }
            }
        }
    }
    __syncwarp();

    // pad with first qualifying index (centroid itself always qualifies)
    int cfull = cnt < NSAMPLE ? cnt : NSAMPLE;
    int first = sel[w][0];
    __syncwarp();
    if (lane >= cfull) sel[w][lane] = first;
    __syncwarp();

    float* op = new_points + ((size_t)(b * NPOINT + m)) * NSAMPLE * OUTCH;

    // centered xyz: lane handles its own sample (small, scattered)
    {
        const int idx = sel[w][lane];
        op[lane * OUTCH + 0] = __fsub_rn(__ldg(xb + idx * 3 + 0), sx);
        op[lane * OUTCH + 1] = __fsub_rn(__ldg(xb + idx * 3 + 1), sy);
        op[lane * OUTCH + 2] = __fsub_rn(__ldg(xb + idx * 3 + 2), sz);
    }

    // features: channel-major — per sample, warp reads one 256B row coalesced
    // and writes 64 consecutive floats (2 per lane)
    const float* pb = points + (size_t)b * NN * DD;
#pragma unroll 4
    for (int s = 0; s < NSAMPLE; s++) {
        int is = sel[w][s];                       // smem broadcast
        float2 v = __ldg((const float2*)(pb + (size_t)is * DD) + lane);
        op[s * OUTCH + 3 + 2 * lane]     = v.x;
        op[s * OUTCH + 3 + 2 * lane + 1] = v.y;
    }
}

// ---------------------------------------------------------------------------
extern "C" void kernel_launch(void* const* d_in, const int* in_sizes, int n_in,
                              void* d_out, int out_size) {
    const float* xyz    = (const float*)d_in[0];
    const float* points = (const float*)d_in[1];

    float* new_xyz    = (float*)d_out;
    float* new_points = (float*)d_out + (size_t)BB * NPOINT * 3;

    fps_kernel<<<BB, 1024>>>(xyz, new_xyz);
    ball_kernel<<<(BB * NPOINT) / 8, 256>>>(xyz, points, new_xyz, new_points);
}